// round 1
// baseline (speedup 1.0000x reference)
#include <cuda_runtime.h>
#include <cuda_bf16.h>

#define DD 128
#define MAXN 100000

static __device__ __align__(16) float g_dinv[MAXN];
static __device__ __align__(16) float g_h[MAXN * DD];
static __device__ __align__(16) float g_agg[MAXN * DD];

// ---------------------------------------------------------------------------
// degree + dinv
// ---------------------------------------------------------------------------
__global__ void deg_kernel(const int* __restrict__ dst, int E) {
    int e = blockIdx.x * blockDim.x + threadIdx.x;
    if (e < E) atomicAdd(&g_dinv[dst[e]], 1.0f);
}

__global__ void dinv_kernel(int n) {
    int i = blockIdx.x * blockDim.x + threadIdx.x;
    if (i < n) {
        float d = g_dinv[i];
        g_dinv[i] = (d > 0.0f) ? rsqrtf(d) : 0.0f;
    }
}

// ---------------------------------------------------------------------------
// GEMM: out[n,128] = act(A[n,128]) @ W[128,128]
// FUSE: act(a) = relu(a + bias[k]) applied to A elements on load.
// Block: 256 threads, 64 output rows, full K=128 and N=128 in shared.
// ---------------------------------------------------------------------------
template <bool FUSE>
__global__ void gemm128_kernel(const float* __restrict__ A,
                               const float* __restrict__ W,
                               const float* __restrict__ bias,
                               float* __restrict__ out, int n) {
    extern __shared__ float smem[];
    float* Ws = smem;               // 128*128
    float* As = smem + DD * DD;     // 64*128
    float4* Ws4 = (float4*)Ws;
    float4* As4 = (float4*)As;

    int tid = threadIdx.x;
    const float4* W4 = (const float4*)W;
#pragma unroll
    for (int i = 0; i < 16; i++) Ws4[tid + i * 256] = W4[tid + i * 256];

    int row0 = blockIdx.x * 64;
#pragma unroll
    for (int i = 0; i < 8; i++) {
        int v = tid + i * 256;          // [0, 2048)
        int r = v >> 5;                 // row within tile
        int c4 = v & 31;                // float4 col
        int grow = row0 + r;
        float4 a = make_float4(0.f, 0.f, 0.f, 0.f);
        if (grow < n) {
            a = ((const float4*)A)[grow * 32 + c4];
            if (FUSE) {
                int c = c4 * 4;
                a.x = fmaxf(a.x + bias[c + 0], 0.f);
                a.y = fmaxf(a.y + bias[c + 1], 0.f);
                a.z = fmaxf(a.z + bias[c + 2], 0.f);
                a.w = fmaxf(a.w + bias[c + 3], 0.f);
            }
        }
        As4[v] = a;
    }
    __syncthreads();

    int tx = tid & 31;    // float4 column
    int ty = tid >> 5;    // base row (0..7)
    float4 acc[8];
#pragma unroll
    for (int j = 0; j < 8; j++) acc[j] = make_float4(0.f, 0.f, 0.f, 0.f);

#pragma unroll 4
    for (int k = 0; k < DD; k++) {
        float4 b = Ws4[k * 32 + tx];
#pragma unroll
        for (int j = 0; j < 8; j++) {
            float a = As[(ty + 8 * j) * DD + k];   // warp-uniform broadcast
            acc[j].x += a * b.x;
            acc[j].y += a * b.y;
            acc[j].z += a * b.z;
            acc[j].w += a * b.w;
        }
    }

#pragma unroll
    for (int j = 0; j < 8; j++) {
        int grow = row0 + ty + 8 * j;
        if (grow < n) ((float4*)out)[grow * 32 + tx] = acc[j];
    }
}

// ---------------------------------------------------------------------------
// Edge scatter: agg[dst] += dinv[src]*dinv[dst] * h[src]
// One warp per edge, float4 per lane, vectored RED (red.global.add.v4.f32).
// ---------------------------------------------------------------------------
__global__ void scatter_kernel(const float* __restrict__ h,
                               const int* __restrict__ src,
                               const int* __restrict__ dst,
                               float* __restrict__ agg, int E) {
    int gw = (blockIdx.x * blockDim.x + threadIdx.x) >> 5;
    int lane = threadIdx.x & 31;
    if (gw >= E) return;
    int s = __ldg(&src[gw]);
    int d = __ldg(&dst[gw]);
    float coef = g_dinv[s] * g_dinv[d];
    float4 v = ((const float4*)h)[s * 32 + lane];
    v.x *= coef; v.y *= coef; v.z *= coef; v.w *= coef;
    float* p = agg + (size_t)d * DD + lane * 4;
    asm volatile("red.global.add.v4.f32 [%0], {%1, %2, %3, %4};"
                 :: "l"(p), "f"(v.x), "f"(v.y), "f"(v.z), "f"(v.w)
                 : "memory");
}

// ---------------------------------------------------------------------------
// Scoring: out[e] = (z[head]+b2)^T  W[rel]  (z[tail]+b2)
// One warp per edge (8 edges per 256-thread block).
// Thread lane covers 4 f-columns; accumulate c[f] = sum_d zh[d]*W[d,f] with
// coalesced float4 loads (rel_W is 1 MB, L2-resident).
// ---------------------------------------------------------------------------
__global__ void score_kernel(const float* __restrict__ z,
                             const float* __restrict__ b2,
                             const float* __restrict__ relW,
                             const int* __restrict__ rel,
                             const int* __restrict__ head,
                             const int* __restrict__ tail,
                             float* __restrict__ out, int ES) {
    __shared__ float zh[8][DD];
    int warp = threadIdx.x >> 5;
    int lane = threadIdx.x & 31;
    int e = blockIdx.x * 8 + warp;
    if (e >= ES) return;

    int r = __ldg(&rel[e]);
    int hh = __ldg(&head[e]);
    int tt = __ldg(&tail[e]);

#pragma unroll
    for (int i = 0; i < 4; i++) {
        int c = lane + i * 32;
        zh[warp][c] = z[(size_t)hh * DD + c] + b2[c];
    }
    __syncwarp();

    const float4* W4 = (const float4*)(relW + (size_t)r * DD * DD);
    float4 acc = make_float4(0.f, 0.f, 0.f, 0.f);
#pragma unroll 8
    for (int d = 0; d < DD; d++) {
        float s = zh[warp][d];
        float4 w = W4[d * 32 + lane];
        acc.x += s * w.x;
        acc.y += s * w.y;
        acc.z += s * w.z;
        acc.w += s * w.w;
    }

    float4 zt = ((const float4*)z)[(size_t)tt * 32 + lane];
    float4 b4 = ((const float4*)b2)[lane];
    float part = (zt.x + b4.x) * acc.x + (zt.y + b4.y) * acc.y +
                 (zt.z + b4.z) * acc.z + (zt.w + b4.w) * acc.w;
#pragma unroll
    for (int off = 16; off; off >>= 1)
        part += __shfl_down_sync(0xffffffff, part, off);
    if (lane == 0) out[e] = part;
}

// ---------------------------------------------------------------------------
extern "C" void kernel_launch(void* const* d_in, const int* in_sizes, int n_in,
                              void* d_out, int out_size) {
    const float* x0   = (const float*)d_in[0];
    const float* W1   = (const float*)d_in[1];
    const float* b1   = (const float*)d_in[2];
    const float* W2   = (const float*)d_in[3];
    const float* b2   = (const float*)d_in[4];
    const float* relW = (const float*)d_in[5];
    const int*   ei   = (const int*)d_in[6];
    const int*   rel  = (const int*)d_in[7];
    const int*   head = (const int*)d_in[8];
    const int*   tail = (const int*)d_in[9];

    int N  = in_sizes[0] / DD;
    int E  = in_sizes[6] / 2;
    int ES = in_sizes[7];
    const int* src = ei;
    const int* dst = ei + E;

    float *dinv_p, *h_p, *agg_p;
    cudaGetSymbolAddress((void**)&dinv_p, g_dinv);
    cudaGetSymbolAddress((void**)&h_p, g_h);
    cudaGetSymbolAddress((void**)&agg_p, g_agg);

    size_t smem = (size_t)(DD * DD + 64 * DD) * sizeof(float);  // 96 KB
    cudaFuncSetAttribute(gemm128_kernel<false>,
                         cudaFuncAttributeMaxDynamicSharedMemorySize, (int)smem);
    cudaFuncSetAttribute(gemm128_kernel<true>,
                         cudaFuncAttributeMaxDynamicSharedMemorySize, (int)smem);

    // degree -> dinv
    cudaMemsetAsync(dinv_p, 0, (size_t)N * sizeof(float), 0);
    deg_kernel<<<(E + 255) / 256, 256>>>(dst, E);
    dinv_kernel<<<(N + 255) / 256, 256>>>(N);

    // layer 1: h = x0 @ W1 ; agg = scatter(norm * h[src] -> dst)
    gemm128_kernel<false><<<(N + 63) / 64, 256, smem>>>(x0, W1, nullptr, h_p, N);
    cudaMemsetAsync(agg_p, 0, (size_t)N * DD * sizeof(float), 0);
    {
        long long total = (long long)E * 32;
        scatter_kernel<<<(unsigned)((total + 255) / 256), 256>>>(h_p, src, dst, agg_p, E);
    }

    // layer 2: h2 = relu(agg + b1) @ W2 ; agg = scatter(norm * h2[src] -> dst)
    gemm128_kernel<true><<<(N + 63) / 64, 256, smem>>>(agg_p, W2, b1, h_p, N);
    cudaMemsetAsync(agg_p, 0, (size_t)N * DD * sizeof(float), 0);
    {
        long long total = (long long)E * 32;
        scatter_kernel<<<(unsigned)((total + 255) / 256), 256>>>(h_p, src, dst, agg_p, E);
    }

    // scoring: z = agg + b2 ; out[e] = z[head]^T W[rel] z[tail]
    score_kernel<<<(ES + 7) / 8, 256>>>(agg_p, b2, relW, rel, head, tail,
                                        (float*)d_out, ES);
}

// round 2
// speedup vs baseline: 1.2221x; 1.2221x over previous
#include <cuda_runtime.h>

#define DD 128
#define MAXN 100000
#define MAXES 131072
#define NREL 16

static __device__ __align__(16) float g_dinv[MAXN];
static __device__ __align__(16) float g_h[MAXN * DD];
static __device__ __align__(16) float g_agg[MAXN * DD];
static __device__ int g_cnt[NREL];
static __device__ int g_off[NREL + 1];
static __device__ int g_cur[NREL];
static __device__ int g_bucket[MAXES];

// ---------------------------------------------------------------------------
// degree + dinv
// ---------------------------------------------------------------------------
__global__ void deg_kernel(const int* __restrict__ dst, int E) {
    int e = blockIdx.x * blockDim.x + threadIdx.x;
    if (e < E) atomicAdd(&g_dinv[dst[e]], 1.0f);
}

__global__ void dinv_kernel(int n) {
    int i = blockIdx.x * blockDim.x + threadIdx.x;
    if (i < n) {
        float d = g_dinv[i];
        g_dinv[i] = (d > 0.0f) ? rsqrtf(d) : 0.0f;
    }
}

// ---------------------------------------------------------------------------
// GEMM: out[n,128] = act(A[n,128]) @ W[128,128], optionally scaled by dinv[row]
// FUSE_IN:  a -> relu(dinv[row]*a + b1[col])
// SCALE_OUT: out row *= dinv[row]
// ---------------------------------------------------------------------------
template <bool FUSE_IN, bool SCALE_OUT>
__global__ void gemm128_kernel(const float* __restrict__ A,
                               const float* __restrict__ W,
                               const float* __restrict__ bias,
                               float* __restrict__ out, int n) {
    extern __shared__ float smem[];
    float* Ws = smem;               // 128*128
    float* As = smem + DD * DD;     // 64*128
    float4* Ws4 = (float4*)Ws;
    float4* As4 = (float4*)As;

    int tid = threadIdx.x;
    const float4* W4 = (const float4*)W;
#pragma unroll
    for (int i = 0; i < 16; i++) Ws4[tid + i * 256] = W4[tid + i * 256];

    int row0 = blockIdx.x * 64;
#pragma unroll
    for (int i = 0; i < 8; i++) {
        int v = tid + i * 256;          // [0, 2048)
        int r = v >> 5;                 // row within tile
        int c4 = v & 31;                // float4 col
        int grow = row0 + r;
        float4 a = make_float4(0.f, 0.f, 0.f, 0.f);
        if (grow < n) {
            a = ((const float4*)A)[(size_t)grow * 32 + c4];
            if (FUSE_IN) {
                float di = g_dinv[grow];
                int c = c4 * 4;
                a.x = fmaxf(di * a.x + bias[c + 0], 0.f);
                a.y = fmaxf(di * a.y + bias[c + 1], 0.f);
                a.z = fmaxf(di * a.z + bias[c + 2], 0.f);
                a.w = fmaxf(di * a.w + bias[c + 3], 0.f);
            }
        }
        As4[v] = a;
    }
    __syncthreads();

    int tx = tid & 31;    // float4 column
    int ty = tid >> 5;    // base row (0..7)
    float4 acc[8];
#pragma unroll
    for (int j = 0; j < 8; j++) acc[j] = make_float4(0.f, 0.f, 0.f, 0.f);

#pragma unroll 4
    for (int k = 0; k < DD; k++) {
        float4 b = Ws4[k * 32 + tx];
#pragma unroll
        for (int j = 0; j < 8; j++) {
            float a = As[(ty + 8 * j) * DD + k];   // warp-uniform broadcast
            acc[j].x += a * b.x;
            acc[j].y += a * b.y;
            acc[j].z += a * b.z;
            acc[j].w += a * b.w;
        }
    }

#pragma unroll
    for (int j = 0; j < 8; j++) {
        int grow = row0 + ty + 8 * j;
        if (grow < n) {
            if (SCALE_OUT) {
                float di = g_dinv[grow];
                acc[j].x *= di; acc[j].y *= di; acc[j].z *= di; acc[j].w *= di;
            }
            ((float4*)out)[(size_t)grow * 32 + tx] = acc[j];
        }
    }
}

// ---------------------------------------------------------------------------
// Edge scatter: agg[dst] += h[src]   (h already pre-scaled by dinv[src])
// One warp per 4 edges: 4 independent row gathers in flight (MLP=4).
// ---------------------------------------------------------------------------
__global__ void scatter_kernel(const float4* __restrict__ h4,
                               const int* __restrict__ src,
                               const int* __restrict__ dst,
                               float* __restrict__ agg, int E) {
    int warp = (blockIdx.x * blockDim.x + threadIdx.x) >> 5;
    int lane = threadIdx.x & 31;
    int e0 = warp * 4;
    if (e0 >= E) return;

    int s[4], d[4];
#pragma unroll
    for (int i = 0; i < 4; i++) {
        int e = e0 + i;
        if (e < E) { s[i] = __ldg(&src[e]); d[i] = __ldg(&dst[e]); }
        else s[i] = -1;
    }

    float4 v[4];
#pragma unroll
    for (int i = 0; i < 4; i++)
        if (s[i] >= 0) v[i] = __ldg(&h4[(size_t)s[i] * 32 + lane]);

#pragma unroll
    for (int i = 0; i < 4; i++) {
        if (s[i] >= 0) {
            float* p = agg + (size_t)d[i] * DD + lane * 4;
            asm volatile("red.global.add.v4.f32 [%0], {%1, %2, %3, %4};"
                         :: "l"(p), "f"(v[i].x), "f"(v[i].y), "f"(v[i].z), "f"(v[i].w)
                         : "memory");
        }
    }
}

// ---------------------------------------------------------------------------
// Relation bucketing: count -> prefix -> place
// ---------------------------------------------------------------------------
__global__ void count_kernel(const int* __restrict__ rel, int ES) {
    int e = blockIdx.x * blockDim.x + threadIdx.x;
    if (e < ES) atomicAdd(&g_cnt[rel[e]], 1);
}

__global__ void prefix_kernel() {
    if (threadIdx.x == 0) {
        int acc = 0;
        for (int i = 0; i < NREL; i++) {
            g_off[i] = acc;
            g_cur[i] = acc;
            acc += g_cnt[i];
        }
        g_off[NREL] = acc;
    }
}

__global__ void place_kernel(const int* __restrict__ rel, int ES) {
    int e = blockIdx.x * blockDim.x + threadIdx.x;
    if (e < ES) {
        int pos = atomicAdd(&g_cur[rel[e]], 1);
        g_bucket[pos] = e;
    }
}

// ---------------------------------------------------------------------------
// Scoring (relation-grouped): out[e] = zh^T W[r] zt,  zh/zt = dinv*agg + b2
// Block = 64 edges of one relation; W[r] staged in smem once.
// grid = (NREL, ceil(ES/64)); blocks past a relation's count exit early.
// ---------------------------------------------------------------------------
__global__ void score_kernel(const float* __restrict__ z,
                             const float* __restrict__ b2,
                             const float* __restrict__ relW,
                             const int* __restrict__ head,
                             const int* __restrict__ tail,
                             float* __restrict__ out, int ES) {
    extern __shared__ float smem[];
    float* Ws = smem;               // 128*128
    float* As = smem + DD * DD;     // 64*128
    __shared__ int s_eid[64];
    __shared__ int s_head[64];
    __shared__ int s_tail[64];
    __shared__ __align__(16) float s_b2[DD];

    int r = blockIdx.x;
    int beg = g_off[r], end = g_off[r + 1];
    int base = beg + (int)blockIdx.y * 64;
    if (base >= end) return;
    int nb = min(64, end - base);
    int tid = threadIdx.x;

    // Stage W[r] (64 KB)
    const float4* W4 = (const float4*)(relW + (size_t)r * DD * DD);
    float4* Ws4 = (float4*)Ws;
#pragma unroll
    for (int i = 0; i < 16; i++) Ws4[tid + i * 256] = __ldg(&W4[tid + i * 256]);

    if (tid < DD) s_b2[tid] = b2[tid];
    if (tid < 64) {
        int e = -1, hh = 0, tt = 0;
        if (tid < nb) {
            e = g_bucket[base + tid];
            hh = __ldg(&head[e]);
            tt = __ldg(&tail[e]);
        }
        s_eid[tid] = e; s_head[tid] = hh; s_tail[tid] = tt;
    }
    __syncthreads();

    // Gather zh rows into As
    float4* As4 = (float4*)As;
    const float4* z4 = (const float4*)z;
    const float4* b24 = (const float4*)s_b2;
#pragma unroll
    for (int i = 0; i < 8; i++) {
        int v = tid + i * 256;
        int rr = v >> 5, c4 = v & 31;
        float4 a = make_float4(0.f, 0.f, 0.f, 0.f);
        if (rr < nb) {
            int hh = s_head[rr];
            float di = g_dinv[hh];
            float4 x = __ldg(&z4[(size_t)hh * 32 + c4]);
            float4 b = b24[c4];
            a.x = di * x.x + b.x;
            a.y = di * x.y + b.y;
            a.z = di * x.z + b.z;
            a.w = di * x.w + b.w;
        }
        As4[v] = a;
    }
    __syncthreads();

    int tx = tid & 31;
    int ty = tid >> 5;
    float4 acc[8];
#pragma unroll
    for (int j = 0; j < 8; j++) acc[j] = make_float4(0.f, 0.f, 0.f, 0.f);

#pragma unroll 4
    for (int k = 0; k < DD; k++) {
        float4 w = Ws4[k * 32 + tx];
#pragma unroll
        for (int j = 0; j < 8; j++) {
            float a = As[(ty + 8 * j) * DD + k];
            acc[j].x += a * w.x;
            acc[j].y += a * w.y;
            acc[j].z += a * w.z;
            acc[j].w += a * w.w;
        }
    }

    // Dot each row's (zh W) with zt, warp-reduce, write to original edge slot
#pragma unroll
    for (int j = 0; j < 8; j++) {
        int row = ty + 8 * j;
        float part = 0.f;
        if (row < nb) {
            int tt = s_tail[row];
            float di = g_dinv[tt];
            float4 zt = __ldg(&z4[(size_t)tt * 32 + tx]);
            float4 b = b24[tx];
            float zx = di * zt.x + b.x;
            float zy = di * zt.y + b.y;
            float zz = di * zt.z + b.z;
            float zw = di * zt.w + b.w;
            part = acc[j].x * zx + acc[j].y * zy + acc[j].z * zz + acc[j].w * zw;
        }
#pragma unroll
        for (int off = 16; off; off >>= 1)
            part += __shfl_down_sync(0xffffffff, part, off);
        if (tx == 0 && row < nb) out[s_eid[row]] = part;
    }
}

// ---------------------------------------------------------------------------
extern "C" void kernel_launch(void* const* d_in, const int* in_sizes, int n_in,
                              void* d_out, int out_size) {
    const float* x0   = (const float*)d_in[0];
    const float* W1   = (const float*)d_in[1];
    const float* b1   = (const float*)d_in[2];
    const float* W2   = (const float*)d_in[3];
    const float* b2   = (const float*)d_in[4];
    const float* relW = (const float*)d_in[5];
    const int*   ei   = (const int*)d_in[6];
    const int*   rel  = (const int*)d_in[7];
    const int*   head = (const int*)d_in[8];
    const int*   tail = (const int*)d_in[9];

    int N  = in_sizes[0] / DD;
    int E  = in_sizes[6] / 2;
    int ES = in_sizes[7];
    const int* src = ei;
    const int* dst = ei + E;

    float *dinv_p, *h_p, *agg_p;
    int* cnt_p;
    cudaGetSymbolAddress((void**)&dinv_p, g_dinv);
    cudaGetSymbolAddress((void**)&h_p, g_h);
    cudaGetSymbolAddress((void**)&agg_p, g_agg);
    cudaGetSymbolAddress((void**)&cnt_p, g_cnt);

    size_t smem = (size_t)(DD * DD + 64 * DD) * sizeof(float);  // 96 KB
    cudaFuncSetAttribute(gemm128_kernel<false, true>,
                         cudaFuncAttributeMaxDynamicSharedMemorySize, (int)smem);
    cudaFuncSetAttribute(gemm128_kernel<true, true>,
                         cudaFuncAttributeMaxDynamicSharedMemorySize, (int)smem);
    cudaFuncSetAttribute(score_kernel,
                         cudaFuncAttributeMaxDynamicSharedMemorySize, (int)smem);

    // degree -> dinv
    cudaMemsetAsync(dinv_p, 0, (size_t)N * sizeof(float), 0);
    cudaMemsetAsync(cnt_p, 0, NREL * sizeof(int), 0);
    deg_kernel<<<(E + 255) / 256, 256>>>(dst, E);
    dinv_kernel<<<(N + 255) / 256, 256>>>(N);

    // relation bucketing (independent of the GCN pipeline, enqueue early)
    count_kernel<<<(ES + 255) / 256, 256>>>(rel, ES);
    prefix_kernel<<<1, 32>>>();
    place_kernel<<<(ES + 255) / 256, 256>>>(rel, ES);

    // layer 1: h = dinv * (x0 @ W1) ; agg = scatter(h[src] -> dst)
    gemm128_kernel<false, true><<<(N + 63) / 64, 256, smem>>>(x0, W1, nullptr, h_p, N);
    cudaMemsetAsync(agg_p, 0, (size_t)N * DD * sizeof(float), 0);
    {
        int warps = (E + 3) / 4;
        int blocks = (warps + 7) / 8;
        scatter_kernel<<<blocks, 256>>>((const float4*)h_p, src, dst, agg_p, E);
    }

    // layer 2: h2 = dinv * (relu(dinv*agg + b1) @ W2) ; agg = scatter(h2[src] -> dst)
    gemm128_kernel<true, true><<<(N + 63) / 64, 256, smem>>>(agg_p, W2, b1, h_p, N);
    cudaMemsetAsync(agg_p, 0, (size_t)N * DD * sizeof(float), 0);
    {
        int warps = (E + 3) / 4;
        int blocks = (warps + 7) / 8;
        scatter_kernel<<<blocks, 256>>>((const float4*)h_p, src, dst, agg_p, E);
    }

    // scoring: z = dinv*agg + b2 ; out[e] = z[head]^T W[rel] z[tail]
    {
        dim3 grid(NREL, (ES + 63) / 64);
        score_kernel<<<grid, 256, smem>>>(agg_p, b2, relW, head, tail,
                                          (float*)d_out, ES);
    }
}

// round 3
// speedup vs baseline: 1.6579x; 1.3565x over previous
#include <cuda_runtime.h>

#define DD 128
#define MAXN 100000
#define MAXE 1700000
#define MAXES 131072
#define NREL 16
#define SCAN_CHUNK 1024
#define MAX_CHUNKS ((MAXN + SCAN_CHUNK - 1) / SCAN_CHUNK)

static __device__ __align__(16) float g_dinv[MAXN];
static __device__ __align__(16) float g_h[MAXN * DD];
static __device__ __align__(16) float g_agg[MAXN * DD];
static __device__ int g_deg[MAXN];
static __device__ int g_rowptr[MAXN + 1];
static __device__ int g_cur[MAXN];
static __device__ int g_srcs[MAXE];
static __device__ int g_blksum[MAX_CHUNKS];
static __device__ int g_cnt[NREL];
static __device__ int g_off[NREL + 1];
static __device__ int g_rcur[NREL];
static __device__ int g_bucket[MAXES];

// ---------------------------------------------------------------------------
// Counting sort by dst: count -> scan (3 kernels) -> place
// ---------------------------------------------------------------------------
__global__ void count_deg_kernel(const int* __restrict__ dst, int E) {
    int e = blockIdx.x * blockDim.x + threadIdx.x;
    if (e < E) atomicAdd(&g_deg[dst[e]], 1);
}

// partial sums per chunk of 1024 bins
__global__ void scan1_kernel(int n) {
    __shared__ int wsum[8];
    int chunk = blockIdx.x;
    int tid = threadIdx.x;
    int s = 0;
#pragma unroll
    for (int i = 0; i < 4; i++) {
        int idx = chunk * SCAN_CHUNK + tid + i * 256;
        if (idx < n) s += g_deg[idx];
    }
#pragma unroll
    for (int off = 16; off; off >>= 1) s += __shfl_down_sync(0xffffffffu, s, off);
    if ((tid & 31) == 0) wsum[tid >> 5] = s;
    __syncthreads();
    if (tid == 0) {
        int a = 0;
#pragma unroll
        for (int i = 0; i < 8; i++) a += wsum[i];
        g_blksum[chunk] = a;
    }
}

// exclusive scan of chunk sums (single thread; <=98 chunks)
__global__ void scan2_kernel(int nchunks, int n) {
    if (threadIdx.x == 0) {
        int a = 0;
        for (int i = 0; i < nchunks; i++) {
            int t = g_blksum[i];
            g_blksum[i] = a;
            a += t;
        }
        g_rowptr[n] = a;
    }
}

// per-chunk exclusive scan + write rowptr/cur + dinv
__global__ void scan3_kernel(int n) {
    __shared__ int wsum[8];
    int chunk = blockIdx.x;
    int tid = threadIdx.x;
    int lane = tid & 31, w = tid >> 5;
    int base0 = chunk * SCAN_CHUNK + tid * 4;
    int v[4];
    int s = 0;
#pragma unroll
    for (int j = 0; j < 4; j++) {
        int idx = base0 + j;
        v[j] = (idx < n) ? g_deg[idx] : 0;
        s += v[j];
    }
    int pre = s;
#pragma unroll
    for (int off = 1; off < 32; off <<= 1) {
        int t = __shfl_up_sync(0xffffffffu, pre, off);
        if (lane >= off) pre += t;
    }
    if (lane == 31) wsum[w] = pre;
    __syncthreads();
    if (tid == 0) {
        int a = 0;
#pragma unroll
        for (int i = 0; i < 8; i++) { int t = wsum[i]; wsum[i] = a; a += t; }
    }
    __syncthreads();
    int excl = pre - s + wsum[w] + g_blksum[chunk];
#pragma unroll
    for (int j = 0; j < 4; j++) {
        int idx = base0 + j;
        if (idx < n) {
            g_rowptr[idx] = excl;
            g_cur[idx] = excl;
            g_dinv[idx] = (v[j] > 0) ? rsqrtf((float)v[j]) : 0.0f;
            excl += v[j];
        }
    }
}

__global__ void place_kernel(const int* __restrict__ src,
                             const int* __restrict__ dst, int E) {
    int e = blockIdx.x * blockDim.x + threadIdx.x;
    if (e < E) {
        int pos = atomicAdd(&g_cur[dst[e]], 1);
        g_srcs[pos] = src[e];
    }
}

// ---------------------------------------------------------------------------
// GEMM: out[n,128] = act(A[n,128]) @ W[128,128], optionally scaled by dinv[row]
// FUSE_IN:  a -> relu(dinv[row]*a + b1[col]) ; SCALE_OUT: out row *= dinv[row]
// ---------------------------------------------------------------------------
template <bool FUSE_IN, bool SCALE_OUT>
__global__ void gemm128_kernel(const float* __restrict__ A,
                               const float* __restrict__ W,
                               const float* __restrict__ bias,
                               float* __restrict__ out, int n) {
    extern __shared__ float smem[];
    float* Ws = smem;               // 128*128
    float* As = smem + DD * DD;     // 64*128
    float4* Ws4 = (float4*)Ws;
    float4* As4 = (float4*)As;

    int tid = threadIdx.x;
    const float4* W4 = (const float4*)W;
#pragma unroll
    for (int i = 0; i < 16; i++) Ws4[tid + i * 256] = W4[tid + i * 256];

    int row0 = blockIdx.x * 64;
#pragma unroll
    for (int i = 0; i < 8; i++) {
        int v = tid + i * 256;
        int r = v >> 5;
        int c4 = v & 31;
        int grow = row0 + r;
        float4 a = make_float4(0.f, 0.f, 0.f, 0.f);
        if (grow < n) {
            a = ((const float4*)A)[(size_t)grow * 32 + c4];
            if (FUSE_IN) {
                float di = g_dinv[grow];
                int c = c4 * 4;
                a.x = fmaxf(di * a.x + bias[c + 0], 0.f);
                a.y = fmaxf(di * a.y + bias[c + 1], 0.f);
                a.z = fmaxf(di * a.z + bias[c + 2], 0.f);
                a.w = fmaxf(di * a.w + bias[c + 3], 0.f);
            }
        }
        As4[v] = a;
    }
    __syncthreads();

    int tx = tid & 31;
    int ty = tid >> 5;
    float4 acc[8];
#pragma unroll
    for (int j = 0; j < 8; j++) acc[j] = make_float4(0.f, 0.f, 0.f, 0.f);

#pragma unroll 4
    for (int k = 0; k < DD; k++) {
        float4 b = Ws4[k * 32 + tx];
#pragma unroll
        for (int j = 0; j < 8; j++) {
            float a = As[(ty + 8 * j) * DD + k];
            acc[j].x += a * b.x;
            acc[j].y += a * b.y;
            acc[j].z += a * b.z;
            acc[j].w += a * b.w;
        }
    }

#pragma unroll
    for (int j = 0; j < 8; j++) {
        int grow = row0 + ty + 8 * j;
        if (grow < n) {
            if (SCALE_OUT) {
                float di = g_dinv[grow];
                acc[j].x *= di; acc[j].y *= di; acc[j].z *= di; acc[j].w *= di;
            }
            ((float4*)out)[(size_t)grow * 32 + tx] = acc[j];
        }
    }
}

// ---------------------------------------------------------------------------
// CSR gather: agg[v] = sum_{e in csr(v)} h[srcs[e]]   (h pre-scaled by dinv[src])
// One warp per dst node; register accumulation; single direct store.
// ---------------------------------------------------------------------------
__global__ void gather_kernel(const float4* __restrict__ h4,
                              float4* __restrict__ agg4, int n) {
    int v = (blockIdx.x * blockDim.x + threadIdx.x) >> 5;
    int lane = threadIdx.x & 31;
    if (v >= n) return;
    int beg = g_rowptr[v];
    int end = g_rowptr[v + 1];
    float4 acc = make_float4(0.f, 0.f, 0.f, 0.f);
    int i = beg;
    for (; i + 4 <= end; i += 4) {
        int s0 = __ldg(&g_srcs[i + 0]);
        int s1 = __ldg(&g_srcs[i + 1]);
        int s2 = __ldg(&g_srcs[i + 2]);
        int s3 = __ldg(&g_srcs[i + 3]);
        float4 a0 = __ldg(&h4[(size_t)s0 * 32 + lane]);
        float4 a1 = __ldg(&h4[(size_t)s1 * 32 + lane]);
        float4 a2 = __ldg(&h4[(size_t)s2 * 32 + lane]);
        float4 a3 = __ldg(&h4[(size_t)s3 * 32 + lane]);
        acc.x += a0.x + a1.x + a2.x + a3.x;
        acc.y += a0.y + a1.y + a2.y + a3.y;
        acc.z += a0.z + a1.z + a2.z + a3.z;
        acc.w += a0.w + a1.w + a2.w + a3.w;
    }
    for (; i < end; i++) {
        int s = __ldg(&g_srcs[i]);
        float4 a = __ldg(&h4[(size_t)s * 32 + lane]);
        acc.x += a.x; acc.y += a.y; acc.z += a.z; acc.w += a.w;
    }
    agg4[(size_t)v * 32 + lane] = acc;
}

// ---------------------------------------------------------------------------
// Relation bucketing
// ---------------------------------------------------------------------------
__global__ void rcount_kernel(const int* __restrict__ rel, int ES) {
    int e = blockIdx.x * blockDim.x + threadIdx.x;
    if (e < ES) atomicAdd(&g_cnt[rel[e]], 1);
}

__global__ void rprefix_kernel() {
    if (threadIdx.x == 0) {
        int acc = 0;
        for (int i = 0; i < NREL; i++) {
            g_off[i] = acc;
            g_rcur[i] = acc;
            acc += g_cnt[i];
        }
        g_off[NREL] = acc;
    }
}

__global__ void rplace_kernel(const int* __restrict__ rel, int ES) {
    int e = blockIdx.x * blockDim.x + threadIdx.x;
    if (e < ES) {
        int pos = atomicAdd(&g_rcur[rel[e]], 1);
        g_bucket[pos] = e;
    }
}

// ---------------------------------------------------------------------------
// Scoring (relation-grouped): out[e] = zh^T W[r] zt,  zh/zt = dinv*agg + b2
// ---------------------------------------------------------------------------
__global__ void score_kernel(const float* __restrict__ z,
                             const float* __restrict__ b2,
                             const float* __restrict__ relW,
                             const int* __restrict__ head,
                             const int* __restrict__ tail,
                             float* __restrict__ out, int ES) {
    extern __shared__ float smem[];
    float* Ws = smem;               // 128*128
    float* As = smem + DD * DD;     // 64*128
    __shared__ int s_eid[64];
    __shared__ int s_head[64];
    __shared__ int s_tail[64];
    __shared__ __align__(16) float s_b2[DD];

    int r = blockIdx.x;
    int beg = g_off[r], end = g_off[r + 1];
    int base = beg + (int)blockIdx.y * 64;
    if (base >= end) return;
    int nb = min(64, end - base);
    int tid = threadIdx.x;

    const float4* W4 = (const float4*)(relW + (size_t)r * DD * DD);
    float4* Ws4 = (float4*)Ws;
#pragma unroll
    for (int i = 0; i < 16; i++) Ws4[tid + i * 256] = __ldg(&W4[tid + i * 256]);

    if (tid < DD) s_b2[tid] = b2[tid];
    if (tid < 64) {
        int e = -1, hh = 0, tt = 0;
        if (tid < nb) {
            e = g_bucket[base + tid];
            hh = __ldg(&head[e]);
            tt = __ldg(&tail[e]);
        }
        s_eid[tid] = e; s_head[tid] = hh; s_tail[tid] = tt;
    }
    __syncthreads();

    float4* As4 = (float4*)As;
    const float4* z4 = (const float4*)z;
    const float4* b24 = (const float4*)s_b2;
#pragma unroll
    for (int i = 0; i < 8; i++) {
        int v = tid + i * 256;
        int rr = v >> 5, c4 = v & 31;
        float4 a = make_float4(0.f, 0.f, 0.f, 0.f);
        if (rr < nb) {
            int hh = s_head[rr];
            float di = g_dinv[hh];
            float4 x = __ldg(&z4[(size_t)hh * 32 + c4]);
            float4 b = b24[c4];
            a.x = di * x.x + b.x;
            a.y = di * x.y + b.y;
            a.z = di * x.z + b.z;
            a.w = di * x.w + b.w;
        }
        As4[v] = a;
    }
    __syncthreads();

    int tx = tid & 31;
    int ty = tid >> 5;
    float4 acc[8];
#pragma unroll
    for (int j = 0; j < 8; j++) acc[j] = make_float4(0.f, 0.f, 0.f, 0.f);

#pragma unroll 4
    for (int k = 0; k < DD; k++) {
        float4 w = Ws4[k * 32 + tx];
#pragma unroll
        for (int j = 0; j < 8; j++) {
            float a = As[(ty + 8 * j) * DD + k];
            acc[j].x += a * w.x;
            acc[j].y += a * w.y;
            acc[j].z += a * w.z;
            acc[j].w += a * w.w;
        }
    }

#pragma unroll
    for (int j = 0; j < 8; j++) {
        int row = ty + 8 * j;
        float part = 0.f;
        if (row < nb) {
            int tt = s_tail[row];
            float di = g_dinv[tt];
            float4 zt = __ldg(&z4[(size_t)tt * 32 + tx]);
            float4 b = b24[tx];
            part = acc[j].x * (di * zt.x + b.x) + acc[j].y * (di * zt.y + b.y) +
                   acc[j].z * (di * zt.z + b.z) + acc[j].w * (di * zt.w + b.w);
        }
#pragma unroll
        for (int off = 16; off; off >>= 1)
            part += __shfl_down_sync(0xffffffff, part, off);
        if (tx == 0 && row < nb) out[s_eid[row]] = part;
    }
}

// ---------------------------------------------------------------------------
extern "C" void kernel_launch(void* const* d_in, const int* in_sizes, int n_in,
                              void* d_out, int out_size) {
    const float* x0   = (const float*)d_in[0];
    const float* W1   = (const float*)d_in[1];
    const float* b1   = (const float*)d_in[2];
    const float* W2   = (const float*)d_in[3];
    const float* b2   = (const float*)d_in[4];
    const float* relW = (const float*)d_in[5];
    const int*   ei   = (const int*)d_in[6];
    const int*   rel  = (const int*)d_in[7];
    const int*   head = (const int*)d_in[8];
    const int*   tail = (const int*)d_in[9];

    int N  = in_sizes[0] / DD;
    int E  = in_sizes[6] / 2;
    int ES = in_sizes[7];
    const int* src = ei;
    const int* dst = ei + E;

    float *h_p, *agg_p;
    int *deg_p, *cnt_p;
    cudaGetSymbolAddress((void**)&h_p, g_h);
    cudaGetSymbolAddress((void**)&agg_p, g_agg);
    cudaGetSymbolAddress((void**)&deg_p, g_deg);
    cudaGetSymbolAddress((void**)&cnt_p, g_cnt);

    size_t smem = (size_t)(DD * DD + 64 * DD) * sizeof(float);  // 96 KB
    cudaFuncSetAttribute(gemm128_kernel<false, true>,
                         cudaFuncAttributeMaxDynamicSharedMemorySize, (int)smem);
    cudaFuncSetAttribute(gemm128_kernel<true, true>,
                         cudaFuncAttributeMaxDynamicSharedMemorySize, (int)smem);
    cudaFuncSetAttribute(score_kernel,
                         cudaFuncAttributeMaxDynamicSharedMemorySize, (int)smem);

    int nchunks = (N + SCAN_CHUNK - 1) / SCAN_CHUNK;

    // CSR build: count -> scan -> place (also produces dinv)
    cudaMemsetAsync(deg_p, 0, (size_t)N * sizeof(int), 0);
    cudaMemsetAsync(cnt_p, 0, NREL * sizeof(int), 0);
    count_deg_kernel<<<(E + 255) / 256, 256>>>(dst, E);
    scan1_kernel<<<nchunks, 256>>>(N);
    scan2_kernel<<<1, 32>>>(nchunks, N);
    scan3_kernel<<<nchunks, 256>>>(N);
    place_kernel<<<(E + 255) / 256, 256>>>(src, dst, E);

    // relation bucketing (independent)
    rcount_kernel<<<(ES + 255) / 256, 256>>>(rel, ES);
    rprefix_kernel<<<1, 32>>>();
    rplace_kernel<<<(ES + 255) / 256, 256>>>(rel, ES);

    int gather_blocks = (N * 32 + 255) / 256;

    // layer 1: h = dinv * (x0 @ W1) ; agg[v] = sum csr
    gemm128_kernel<false, true><<<(N + 63) / 64, 256, smem>>>(x0, W1, nullptr, h_p, N);
    gather_kernel<<<gather_blocks, 256>>>((const float4*)h_p, (float4*)agg_p, N);

    // layer 2: h2 = dinv * (relu(dinv*agg + b1) @ W2) ; agg = csr gather
    gemm128_kernel<true, true><<<(N + 63) / 64, 256, smem>>>(agg_p, W2, b1, h_p, N);
    gather_kernel<<<gather_blocks, 256>>>((const float4*)h_p, (float4*)agg_p, N);

    // scoring
    {
        dim3 grid(NREL, (ES + 63) / 64);
        score_kernel<<<grid, 256, smem>>>(agg_p, b2, relW, head, tail,
                                          (float*)d_out, ES);
    }
}